// round 15
// baseline (speedup 1.0000x reference)
#include <cuda_runtime.h>
#include <cuda_bf16.h>
#include <cuda_fp16.h>
#include <cstdint>

#define H 128
#define H4 32
#define MAXN 50176   // padded capacity (actual N = 50000)
#define MAXE 655360  // padded capacity (actual E = 640000)
#define TILE_M 64

#define WK_STRIDE 136                  // row stride in halfs (bank-conflict-free)
#define SA_HALFS (64 * WK_STRIDE)      // 8704 halfs per A tile (hi or lo)
#define W_HALFS  (128 * WK_STRIDE)     // 17408 halfs per W tile
#define MLP_SMEM_BYTES ((2 * SA_HALFS + W_HALFS) * 2)   // 69632 B -> 3 CTAs/SM

__device__ float g_x[MAXN * H];
__device__ float g_agg[MAXN * H];
// fp16 weights, pre-transposed [n][k] stride-136: per conv {W1hi, W2hi}
__device__ __align__(16) unsigned short g_wsplit[6 * W_HALFS];
// CSR (dst-sorted) scratch
__device__ int  g_deg[MAXN];
__device__ int  g_rowptr[MAXN + 1];
__device__ int  g_pos[MAXN];
__device__ int  g_bsum[64];
__device__ int2 g_se[MAXE];            // (src, edge_id) sorted by dst

// ---------------------------------------------------------------------------
// helpers
// ---------------------------------------------------------------------------
__device__ __forceinline__ uint32_t pack_fp16(float a, float b) {
    __half2 h = __floats2half2_rn(a, b);
    return *reinterpret_cast<uint32_t*>(&h);
}

__device__ __forceinline__ void split_fp16(float v, float& hi, float& lo) {
    __half h = __float2half_rn(v);
    hi = __half2float(h);
    lo = v - hi;   // then quantized again by pack_fp16
}

__device__ __forceinline__ void mma16(float* c, uint32_t a0, uint32_t a1,
                                      uint32_t a2, uint32_t a3,
                                      uint32_t b0, uint32_t b1) {
    asm("mma.sync.aligned.m16n8k16.row.col.f32.f16.f16.f32 "
        "{%0,%1,%2,%3}, {%4,%5,%6,%7}, {%8,%9}, {%0,%1,%2,%3};"
        : "+f"(c[0]), "+f"(c[1]), "+f"(c[2]), "+f"(c[3])
        : "r"(a0), "r"(a1), "r"(a2), "r"(a3), "r"(b0), "r"(b1));
}

__device__ __forceinline__ void ldsm4(uint32_t& r0, uint32_t& r1,
                                      uint32_t& r2, uint32_t& r3, uint32_t saddr) {
    asm volatile("ldmatrix.sync.aligned.m8n8.x4.shared.b16 {%0,%1,%2,%3}, [%4];"
                 : "=r"(r0), "=r"(r1), "=r"(r2), "=r"(r3) : "r"(saddr));
}

// ---------------------------------------------------------------------------
// CSR build kernels
// ---------------------------------------------------------------------------
__global__ void k_hist(const int* __restrict__ ei, int E) {
    int e = blockIdx.x * blockDim.x + threadIdx.x;
    if (e < E) atomicAdd(&g_deg[ei[E + e]], 1);
}

__global__ void k_scan1(int n) {   // per-block exclusive prescan of g_deg
    __shared__ int sh[1024];
    int i = blockIdx.x * 1024 + threadIdx.x;
    int v = (i < n) ? g_deg[i] : 0;
    sh[threadIdx.x] = v;
    __syncthreads();
    #pragma unroll
    for (int off = 1; off < 1024; off <<= 1) {
        int t = (threadIdx.x >= off) ? sh[threadIdx.x - off] : 0;
        __syncthreads();
        sh[threadIdx.x] += t;
        __syncthreads();
    }
    if (i <= n) g_rowptr[i] = sh[threadIdx.x] - v;   // exclusive within block
    if (threadIdx.x == 1023) g_bsum[blockIdx.x] = sh[1023];
}

__global__ void k_scan2(int nb) {
    if (threadIdx.x == 0) {
        int s = 0;
        for (int b = 0; b < nb; ++b) { int t = g_bsum[b]; g_bsum[b] = s; s += t; }
    }
}

__global__ void k_scan3(int n, int E) {
    int i = blockIdx.x * 1024 + threadIdx.x;
    if (i < n) {
        int v = g_rowptr[i] + g_bsum[blockIdx.x];
        g_rowptr[i] = v;
        g_pos[i] = v;
    }
    if (i == n) g_rowptr[n] = E;
}

__global__ void k_fill(const int* __restrict__ ei, int E) {
    int e = blockIdx.x * blockDim.x + threadIdx.x;
    if (e >= E) return;
    int d = ei[E + e];
    int slot = atomicAdd(&g_pos[d], 1);
    g_se[slot] = make_int2(ei[e], e);
}

// ---------------------------------------------------------------------------
// weight prep: W[k][n] -> fp16 tiles, transposed [n][k] stride-136
// grid = 6 (conv*2 + layer), 256 threads
// ---------------------------------------------------------------------------
__global__ void k_wsplit(const float* __restrict__ W1, const float* __restrict__ W2) {
    int cl = blockIdx.x;               // 0..5 = conv*2 + layer
    int conv = cl >> 1;
    int layer = cl & 1;
    const float* W = layer ? (W2 + (size_t)conv * H * H) : (W1 + (size_t)conv * H * H);
    unsigned short* outHi = g_wsplit + (size_t)cl * W_HALFS;
    for (int idx = threadIdx.x; idx < H * H; idx += blockDim.x) {
        int k = idx >> 7;
        int nn = idx & 127;
        __half hb = __float2half_rn(W[k * H + nn]);
        outHi[nn * WK_STRIDE + k] = *reinterpret_cast<unsigned short*>(&hb);
    }
}

// ---------------------------------------------------------------------------
// x[n] = emb[z[n]]
// ---------------------------------------------------------------------------
__global__ void k_embed(const int* __restrict__ z, const float* __restrict__ emb,
                        float* __restrict__ x, int n) {
    int t = blockIdx.x * blockDim.x + threadIdx.x;
    int row = t >> 5;
    int col = t & 31;
    if (row >= n) return;
    int v = z[row];
    reinterpret_cast<float4*>(x)[row * H4 + col] =
        reinterpret_cast<const float4*>(emb)[v * H4 + col];
}

// ---------------------------------------------------------------------------
// gather phase (CSR, no atomics): agg[v] = x[v] + sum_e relu(x[src_e] + ea[e])
// one warp per node; ea streamed with __ldcs (evict-first), x kept via __ldg
// ---------------------------------------------------------------------------
__global__ void __launch_bounds__(256) k_gather(const float* __restrict__ ea,
                                                const float* __restrict__ x,
                                                float* __restrict__ agg, int n) {
    int v = (blockIdx.x * blockDim.x + threadIdx.x) >> 5;
    int lane = threadIdx.x & 31;
    if (v >= n) return;
    int beg = __ldg(&g_rowptr[v]);
    int end = __ldg(&g_rowptr[v + 1]);
    const float4* xv4 = reinterpret_cast<const float4*>(x);
    const float4* eav = reinterpret_cast<const float4*>(ea);

    float4 acc0 = __ldg(&xv4[(size_t)v * H4 + lane]);
    float4 acc1 = make_float4(0.f, 0.f, 0.f, 0.f);

    int i = beg;
    for (; i + 1 < end; i += 2) {
        int2 s0 = __ldg(&g_se[i]);
        int2 s1 = __ldg(&g_se[i + 1]);
        float4 xs0 = __ldg(&xv4[(size_t)s0.x * H4 + lane]);
        float4 ev0 = __ldcs(&eav[(size_t)s0.y * H4 + lane]);
        float4 xs1 = __ldg(&xv4[(size_t)s1.x * H4 + lane]);
        float4 ev1 = __ldcs(&eav[(size_t)s1.y * H4 + lane]);
        acc0.x += fmaxf(xs0.x + ev0.x, 0.f);
        acc0.y += fmaxf(xs0.y + ev0.y, 0.f);
        acc0.z += fmaxf(xs0.z + ev0.z, 0.f);
        acc0.w += fmaxf(xs0.w + ev0.w, 0.f);
        acc1.x += fmaxf(xs1.x + ev1.x, 0.f);
        acc1.y += fmaxf(xs1.y + ev1.y, 0.f);
        acc1.z += fmaxf(xs1.z + ev1.z, 0.f);
        acc1.w += fmaxf(xs1.w + ev1.w, 0.f);
    }
    if (i < end) {
        int2 s0 = __ldg(&g_se[i]);
        float4 xs0 = __ldg(&xv4[(size_t)s0.x * H4 + lane]);
        float4 ev0 = __ldcs(&eav[(size_t)s0.y * H4 + lane]);
        acc0.x += fmaxf(xs0.x + ev0.x, 0.f);
        acc0.y += fmaxf(xs0.y + ev0.y, 0.f);
        acc0.z += fmaxf(xs0.z + ev0.z, 0.f);
        acc0.w += fmaxf(xs0.w + ev0.w, 0.f);
    }
    acc0.x += acc1.x; acc0.y += acc1.y; acc0.z += acc1.z; acc0.w += acc1.w;
    reinterpret_cast<float4*>(agg)[(size_t)v * H4 + lane] = acc0;
}

// ---------------------------------------------------------------------------
// one 64x128x128 GEMM layer on mma.sync fp16 (2-product split):
//   D = (Ahi + Alo) @ Whi      (drops A@Wlo ~ 2^-12 relative)
// warp computes 32 rows x 32 cols: 2 m-frags (m16) x 4 n-frags (n8).
// Fragment loads via ldmatrix.x4: 6 LDSM vs 24 LDS32 per k-step.
// ---------------------------------------------------------------------------
__device__ __forceinline__ void gemm_layer(uint32_t uAhi, uint32_t uAlo,
                                           uint32_t uWhi,
                                           int rowb, int colb, int lane,
                                           float acc[2][4][4]) {
    // A lane address: r = lane&15, c = (lane>>4)*8  (tiles (0,0),(8,0),(0,8),(8,8))
    const int rA = lane & 15;
    const int cA = (lane >> 4) << 3;
    const uint32_t offA = (uint32_t)(((rowb + rA) * WK_STRIDE + cA) * 2);
    // B lane address for j-pair base j2: n = colb+(j2+(lane>>4))*8+(lane&7),
    // c = (lane&8)?8:0 -> regs {b[j2][0], b[j2][1], b[j2+1][0], b[j2+1][1]}
    const int nB = (lane >> 4) * 8 + (lane & 7);
    const int cB = (lane & 8) ? 8 : 0;
    const uint32_t offB0 = (uint32_t)(((colb + nB) * WK_STRIDE + cB) * 2);
    const uint32_t offB1 = offB0 + (uint32_t)(16 * WK_STRIDE * 2);

    #pragma unroll
    for (int ks = 0; ks < 8; ++ks) {
        const uint32_t k0b = (uint32_t)(ks * 16 * 2);
        uint32_t bh[4][2];
        ldsm4(bh[0][0], bh[0][1], bh[1][0], bh[1][1], uWhi + offB0 + k0b);
        ldsm4(bh[2][0], bh[2][1], bh[3][0], bh[3][1], uWhi + offB1 + k0b);
        #pragma unroll
        for (int m = 0; m < 2; ++m) {
            const uint32_t am = (uint32_t)(m * 16 * WK_STRIDE * 2) + offA + k0b;
            uint32_t ah0, ah1, ah2, ah3, al0, al1, al2, al3;
            ldsm4(ah0, ah1, ah2, ah3, uAhi + am);
            ldsm4(al0, al1, al2, al3, uAlo + am);
            #pragma unroll
            for (int j = 0; j < 4; ++j)
                mma16(acc[m][j], ah0, ah1, ah2, ah3, bh[j][0], bh[j][1]);  // hi
            #pragma unroll
            for (int j = 0; j < 4; ++j)
                mma16(acc[m][j], al0, al1, al2, al3, bh[j][0], bh[j][1]);  // lo
        }
    }
}

// ---------------------------------------------------------------------------
// fused 2-layer MLP on mma.sync fp16 2-product split:
//   h = relu(agg @ W1 + b1);  y = h @ W2 + b2; (relu?) ; out = y + x
// Block: 256 threads, 64-row tile, 3 CTAs/SM (69.6KB smem).
// ---------------------------------------------------------------------------
__global__ void __launch_bounds__(256, 3)
k_mlp(const float* __restrict__ agg, const float* __restrict__ xin,
      const unsigned short* __restrict__ wbase, const float* __restrict__ b1,
      const float* __restrict__ b2, float* __restrict__ xout,
      int n, int relu_out) {
    extern __shared__ __align__(16) unsigned short smh[];
    unsigned short* sAhi = smh;                       // 64 x 136
    unsigned short* sAlo = smh + SA_HALFS;
    unsigned short* sWhi = smh + 2 * SA_HALFS;        // 128 x 136

    const uint32_t sbase = (uint32_t)__cvta_generic_to_shared(smh);
    const uint32_t uAhi = sbase;
    const uint32_t uAlo = sbase + SA_HALFS * 2;
    const uint32_t uWhi = sbase + 2 * SA_HALFS * 2;

    const int tid = threadIdx.x;
    const int lane = tid & 31;
    const int warp = tid >> 5;
    const int rowb = (warp >> 2) * 32;      // 0 or 32
    const int colb = (warp & 3) * 32;       // 0,32,64,96
    const int row0 = blockIdx.x * TILE_M;
    const int kq = lane & 3, nq = lane >> 2;

    // load + split A tile (agg already = scatter_sum + x; pad rows are zero)
    {
        const float4* aggv = reinterpret_cast<const float4*>(agg);
        for (int i = tid; i < 64 * 32; i += 256) {
            int r = i >> 5, kv = i & 31;
            float4 v = aggv[(size_t)(row0 + r) * H4 + kv];
            float h0, l0, h1, l1, h2, l2, h3, l3;
            split_fp16(v.x, h0, l0); split_fp16(v.y, h1, l1);
            split_fp16(v.z, h2, l2); split_fp16(v.w, h3, l3);
            int off = r * WK_STRIDE + kv * 4;
            *reinterpret_cast<uint2*>(sAhi + off) =
                make_uint2(pack_fp16(h0, h1), pack_fp16(h2, h3));
            *reinterpret_cast<uint2*>(sAlo + off) =
                make_uint2(pack_fp16(l0, l1), pack_fp16(l2, l3));
        }
    }
    // load W1 (identical layout -> linear vector copy)
    {
        const uint4* whi = reinterpret_cast<const uint4*>(wbase);
        for (int i = tid; i < W_HALFS / 8; i += 256)
            reinterpret_cast<uint4*>(sWhi)[i] = whi[i];
    }
    __syncthreads();

    float acc[2][4][4];
    #pragma unroll
    for (int m = 0; m < 2; ++m)
        #pragma unroll
        for (int j = 0; j < 4; ++j)
            #pragma unroll
            for (int c = 0; c < 4; ++c) acc[m][j][c] = 0.f;

    gemm_layer(uAhi, uAlo, uWhi, rowb, colb, lane, acc);

    __syncthreads();   // everyone done reading A / W1 slots

    // epilogue 1: h = relu(D + b1) -> split back into sAhi/sAlo; load W2 tile
    #pragma unroll
    for (int j = 0; j < 4; ++j) {
        int n0 = colb + j * 8 + kq * 2;
        float2 bv = *reinterpret_cast<const float2*>(&b1[n0]);
        #pragma unroll
        for (int m = 0; m < 2; ++m) {
            int r = rowb + m * 16 + nq;
            float v0 = fmaxf(acc[m][j][0] + bv.x, 0.f);
            float v1 = fmaxf(acc[m][j][1] + bv.y, 0.f);
            float v2 = fmaxf(acc[m][j][2] + bv.x, 0.f);
            float v3 = fmaxf(acc[m][j][3] + bv.y, 0.f);
            float h0, l0, h1, l1, h2, l2, h3, l3;
            split_fp16(v0, h0, l0); split_fp16(v1, h1, l1);
            split_fp16(v2, h2, l2); split_fp16(v3, h3, l3);
            *reinterpret_cast<uint32_t*>(sAhi + r * WK_STRIDE + n0) = pack_fp16(h0, h1);
            *reinterpret_cast<uint32_t*>(sAlo + r * WK_STRIDE + n0) = pack_fp16(l0, l1);
            *reinterpret_cast<uint32_t*>(sAhi + (r + 8) * WK_STRIDE + n0) = pack_fp16(h2, h3);
            *reinterpret_cast<uint32_t*>(sAlo + (r + 8) * WK_STRIDE + n0) = pack_fp16(l2, l3);
        }
    }
    {
        const uint4* whi = reinterpret_cast<const uint4*>(wbase + W_HALFS);
        for (int i = tid; i < W_HALFS / 8; i += 256)
            reinterpret_cast<uint4*>(sWhi)[i] = whi[i];
    }
    __syncthreads();

    #pragma unroll
    for (int m = 0; m < 2; ++m)
        #pragma unroll
        for (int j = 0; j < 4; ++j)
            #pragma unroll
            for (int c = 0; c < 4; ++c) acc[m][j][c] = 0.f;

    gemm_layer(uAhi, uAlo, uWhi, rowb, colb, lane, acc);

    // epilogue 2: y = D + b2 (+relu) + x ; store to gmem
    #pragma unroll
    for (int j = 0; j < 4; ++j) {
        int n0 = colb + j * 8 + kq * 2;
        float2 bv = *reinterpret_cast<const float2*>(&b2[n0]);
        #pragma unroll
        for (int m = 0; m < 2; ++m) {
            int r = rowb + m * 16 + nq;
            int gr0 = row0 + r;
            int gr1 = gr0 + 8;
            float y0 = acc[m][j][0] + bv.x, y1 = acc[m][j][1] + bv.y;
            float y2 = acc[m][j][2] + bv.x, y3 = acc[m][j][3] + bv.y;
            if (relu_out) {
                y0 = fmaxf(y0, 0.f); y1 = fmaxf(y1, 0.f);
                y2 = fmaxf(y2, 0.f); y3 = fmaxf(y3, 0.f);
            }
            if (gr0 < n) {
                float2 xv = *reinterpret_cast<const float2*>(&xin[(size_t)gr0 * H + n0]);
                *reinterpret_cast<float2*>(&xout[(size_t)gr0 * H + n0]) =
                    make_float2(y0 + xv.x, y1 + xv.y);
            }
            if (gr1 < n) {
                float2 xv = *reinterpret_cast<const float2*>(&xin[(size_t)gr1 * H + n0]);
                *reinterpret_cast<float2*>(&xout[(size_t)gr1 * H + n0]) =
                    make_float2(y2 + xv.x, y3 + xv.y);
            }
        }
    }
}

// ---------------------------------------------------------------------------
extern "C" void kernel_launch(void* const* d_in, const int* in_sizes, int n_in,
                              void* d_out, int out_size) {
    const int*   z   = (const int*)d_in[0];
    const int*   ei  = (const int*)d_in[1];
    const float* ea  = (const float*)d_in[2];
    const float* emb = (const float*)d_in[3];
    const float* W1  = (const float*)d_in[4];
    const float* b1  = (const float*)d_in[5];
    const float* W2  = (const float*)d_in[6];
    const float* b2  = (const float*)d_in[7];
    float* out = (float*)d_out;

    const int n = in_sizes[0];
    const int E = in_sizes[1] / 2;

    float *xbuf, *aggbuf;
    unsigned short* wsplit;
    int* degp;
    cudaGetSymbolAddress((void**)&xbuf, g_x);
    cudaGetSymbolAddress((void**)&aggbuf, g_agg);
    cudaGetSymbolAddress((void**)&wsplit, g_wsplit);
    cudaGetSymbolAddress((void**)&degp, g_deg);

    cudaFuncSetAttribute(k_mlp, cudaFuncAttributeMaxDynamicSharedMemorySize,
                         MLP_SMEM_BYTES);

    // ---- CSR build (once; reused by all 3 convs) ----
    const int NB = (n + 1023) / 1024;
    cudaMemsetAsync(degp, 0, (size_t)n * sizeof(int), 0);
    k_hist<<<(E + 255) / 256, 256>>>(ei, E);
    k_scan1<<<NB, 1024>>>(n);
    k_scan2<<<1, 32>>>(NB);
    k_scan3<<<NB, 1024>>>(n, E);
    k_fill<<<(E + 255) / 256, 256>>>(ei, E);

    // fp16 weights, transposed tile layout
    k_wsplit<<<6, 256>>>(W1, W2);

    // embed
    {
        int threads = n * 32;
        k_embed<<<(threads + 255) / 256, 256>>>(z, emb, xbuf, n);
    }

    const int gatherBlocks = (n * 32 + 255) / 256;   // 1 warp per node
    const int mlpBlocks = (n + TILE_M - 1) / TILE_M;

    for (int i = 0; i < 3; ++i) {
        k_gather<<<gatherBlocks, 256>>>(ea, xbuf, aggbuf, n);
        float* dst = (i == 2) ? out : xbuf;
        k_mlp<<<mlpBlocks, 256, MLP_SMEM_BYTES>>>(aggbuf, xbuf,
                                                  wsplit + (size_t)i * 2 * W_HALFS,
                                                  b1 + i * H, b2 + i * H,
                                                  dst, n, (i < 2) ? 1 : 0);
    }
}

// round 17
// speedup vs baseline: 1.2551x; 1.2551x over previous
#include <cuda_runtime.h>
#include <cuda_bf16.h>
#include <cuda_fp16.h>
#include <cstdint>

#define H 128
#define H4 32
#define MAXN 50176   // padded capacity (actual N = 50000)
#define MAXE 655360  // padded capacity (actual E = 640000)
#define TILE_M 64

#define WK_STRIDE 136                  // row stride in halfs (bank-conflict-free)
#define SA_HALFS (64 * WK_STRIDE)      // 8704 halfs per A tile (hi or lo)
#define W_HALFS  (128 * WK_STRIDE)     // 17408 halfs per W tile
#define MLP_SMEM_BYTES ((2 * SA_HALFS + W_HALFS) * 2)   // 69632 B -> 3 CTAs/SM

__device__ float g_x[MAXN * H];
__device__ float g_agg[MAXN * H];
// fp16 weights, pre-transposed [n][k] stride-136: per conv {W1hi, W2hi}
__device__ __align__(16) unsigned short g_wsplit[6 * W_HALFS];
// CSR (dst-sorted) scratch
__device__ int  g_deg[MAXN];
__device__ int  g_rowptr[MAXN + 1];
__device__ int  g_pos[MAXN];
__device__ int  g_bsum[64];
__device__ int2 g_se[MAXE];            // (src, edge_id) sorted by dst

// ---------------------------------------------------------------------------
// helpers
// ---------------------------------------------------------------------------
__device__ __forceinline__ uint32_t pack_fp16(float a, float b) {
    __half2 h = __floats2half2_rn(a, b);
    return *reinterpret_cast<uint32_t*>(&h);
}

__device__ __forceinline__ void split_fp16(float v, float& hi, float& lo) {
    __half h = __float2half_rn(v);
    hi = __half2float(h);
    lo = v - hi;   // then quantized again by pack_fp16
}

__device__ __forceinline__ uint32_t ld32h(const unsigned short* p, int idx) {
    return *reinterpret_cast<const uint32_t*>(p + idx);   // idx always even
}

__device__ __forceinline__ void mma16(float* c, uint32_t a0, uint32_t a1,
                                      uint32_t a2, uint32_t a3,
                                      uint32_t b0, uint32_t b1) {
    asm("mma.sync.aligned.m16n8k16.row.col.f32.f16.f16.f32 "
        "{%0,%1,%2,%3}, {%4,%5,%6,%7}, {%8,%9}, {%0,%1,%2,%3};"
        : "+f"(c[0]), "+f"(c[1]), "+f"(c[2]), "+f"(c[3])
        : "r"(a0), "r"(a1), "r"(a2), "r"(a3), "r"(b0), "r"(b1));
}

// ---------------------------------------------------------------------------
// merged prologue: hist (blocks [0, HB)), embed (blocks [HB, HB+EB)),
// wsplit (last 6 blocks). All three parts are mutually independent.
// ---------------------------------------------------------------------------
__global__ void k_prep(const int* __restrict__ ei, int E,
                       const int* __restrict__ z, const float* __restrict__ emb,
                       float* __restrict__ x, int n,
                       const float* __restrict__ W1, const float* __restrict__ W2,
                       int HB, int EB) {
    int b = blockIdx.x;
    if (b < HB) {
        int e = b * 256 + threadIdx.x;
        if (e < E) atomicAdd(&g_deg[ei[E + e]], 1);
    } else if (b < HB + EB) {
        int t = (b - HB) * 256 + threadIdx.x;
        int row = t >> 5;
        int col = t & 31;
        if (row >= n) return;
        int v = z[row];
        reinterpret_cast<float4*>(x)[row * H4 + col] =
            reinterpret_cast<const float4*>(emb)[v * H4 + col];
    } else {
        int cl = b - HB - EB;          // 0..5 = conv*2 + layer
        int conv = cl >> 1;
        int layer = cl & 1;
        const float* W = layer ? (W2 + (size_t)conv * H * H)
                               : (W1 + (size_t)conv * H * H);
        unsigned short* outHi = g_wsplit + (size_t)cl * W_HALFS;
        for (int idx = threadIdx.x; idx < H * H; idx += blockDim.x) {
            int k = idx >> 7;
            int nn = idx & 127;
            __half hb = __float2half_rn(W[k * H + nn]);
            outHi[nn * WK_STRIDE + k] = *reinterpret_cast<unsigned short*>(&hb);
        }
    }
}

// ---------------------------------------------------------------------------
// CSR scan kernels
// ---------------------------------------------------------------------------
__global__ void k_scan1(int n) {   // per-block exclusive prescan of g_deg
    __shared__ int sh[1024];
    int i = blockIdx.x * 1024 + threadIdx.x;
    int v = (i < n) ? g_deg[i] : 0;
    sh[threadIdx.x] = v;
    __syncthreads();
    #pragma unroll
    for (int off = 1; off < 1024; off <<= 1) {
        int t = (threadIdx.x >= off) ? sh[threadIdx.x - off] : 0;
        __syncthreads();
        sh[threadIdx.x] += t;
        __syncthreads();
    }
    if (i <= n) g_rowptr[i] = sh[threadIdx.x] - v;   // exclusive within block
    if (threadIdx.x == 1023) g_bsum[blockIdx.x] = sh[1023];
}

// scan2 folded in: every block redundantly prefix-sums the <=64 block sums
__global__ void k_scan3(int n, int E) {
    int s = 0;
    for (int b = 0; b < (int)blockIdx.x; ++b) s += g_bsum[b];
    int i = blockIdx.x * 1024 + threadIdx.x;
    if (i < n) {
        int v = g_rowptr[i] + s;
        g_rowptr[i] = v;
        g_pos[i] = v;
    }
    if (i == n) g_rowptr[n] = E;
}

__global__ void k_fill(const int* __restrict__ ei, int E) {
    int e = blockIdx.x * blockDim.x + threadIdx.x;
    if (e >= E) return;
    int d = ei[E + e];
    int slot = atomicAdd(&g_pos[d], 1);
    g_se[slot] = make_int2(ei[e], e);
}

// ---------------------------------------------------------------------------
// gather phase (CSR, no atomics): agg[v] = x[v] + sum_e relu(x[src_e] + ea[e])
// one warp per node; ea streamed with __ldcs (evict-first), x kept via __ldg
// ---------------------------------------------------------------------------
__global__ void __launch_bounds__(256) k_gather(const float* __restrict__ ea,
                                                const float* __restrict__ x,
                                                float* __restrict__ agg, int n) {
    int v = (blockIdx.x * blockDim.x + threadIdx.x) >> 5;
    int lane = threadIdx.x & 31;
    if (v >= n) return;
    int beg = __ldg(&g_rowptr[v]);
    int end = __ldg(&g_rowptr[v + 1]);
    const float4* xv4 = reinterpret_cast<const float4*>(x);
    const float4* eav = reinterpret_cast<const float4*>(ea);

    float4 acc0 = __ldg(&xv4[(size_t)v * H4 + lane]);
    float4 acc1 = make_float4(0.f, 0.f, 0.f, 0.f);

    int i = beg;
    for (; i + 1 < end; i += 2) {
        int2 s0 = __ldg(&g_se[i]);
        int2 s1 = __ldg(&g_se[i + 1]);
        float4 xs0 = __ldg(&xv4[(size_t)s0.x * H4 + lane]);
        float4 ev0 = __ldcs(&eav[(size_t)s0.y * H4 + lane]);
        float4 xs1 = __ldg(&xv4[(size_t)s1.x * H4 + lane]);
        float4 ev1 = __ldcs(&eav[(size_t)s1.y * H4 + lane]);
        acc0.x += fmaxf(xs0.x + ev0.x, 0.f);
        acc0.y += fmaxf(xs0.y + ev0.y, 0.f);
        acc0.z += fmaxf(xs0.z + ev0.z, 0.f);
        acc0.w += fmaxf(xs0.w + ev0.w, 0.f);
        acc1.x += fmaxf(xs1.x + ev1.x, 0.f);
        acc1.y += fmaxf(xs1.y + ev1.y, 0.f);
        acc1.z += fmaxf(xs1.z + ev1.z, 0.f);
        acc1.w += fmaxf(xs1.w + ev1.w, 0.f);
    }
    if (i < end) {
        int2 s0 = __ldg(&g_se[i]);
        float4 xs0 = __ldg(&xv4[(size_t)s0.x * H4 + lane]);
        float4 ev0 = __ldcs(&eav[(size_t)s0.y * H4 + lane]);
        acc0.x += fmaxf(xs0.x + ev0.x, 0.f);
        acc0.y += fmaxf(xs0.y + ev0.y, 0.f);
        acc0.z += fmaxf(xs0.z + ev0.z, 0.f);
        acc0.w += fmaxf(xs0.w + ev0.w, 0.f);
    }
    acc0.x += acc1.x; acc0.y += acc1.y; acc0.z += acc1.z; acc0.w += acc1.w;
    reinterpret_cast<float4*>(agg)[(size_t)v * H4 + lane] = acc0;
}

// ---------------------------------------------------------------------------
// one 64x128x128 GEMM layer on mma.sync fp16 (2-product split):
//   D = (Ahi + Alo) @ Whi      (drops A@Wlo ~ 2^-12 relative)
// warp computes 32 rows x 32 cols: 2 m-frags (m16) x 4 n-frags (n8).
// ---------------------------------------------------------------------------
__device__ __forceinline__ void gemm_layer(const unsigned short* __restrict__ sAhi,
                                           const unsigned short* __restrict__ sAlo,
                                           const unsigned short* __restrict__ sWhi,
                                           int rowb, int colb, int nq, int kq,
                                           float acc[2][4][4]) {
    #pragma unroll
    for (int ks = 0; ks < 8; ++ks) {
        const int k0 = ks * 16;
        uint32_t bh[4][2];
        #pragma unroll
        for (int j = 0; j < 4; ++j) {
            int off = (colb + j * 8 + nq) * WK_STRIDE + k0 + kq * 2;
            bh[j][0] = ld32h(sWhi, off);
            bh[j][1] = ld32h(sWhi, off + 8);
        }
        #pragma unroll
        for (int m = 0; m < 2; ++m) {
            int base = (rowb + m * 16 + nq) * WK_STRIDE + k0 + kq * 2;
            uint32_t ah0 = ld32h(sAhi, base);
            uint32_t ah1 = ld32h(sAhi, base + 8 * WK_STRIDE);
            uint32_t ah2 = ld32h(sAhi, base + 8);
            uint32_t ah3 = ld32h(sAhi, base + 8 * WK_STRIDE + 8);
            uint32_t al0 = ld32h(sAlo, base);
            uint32_t al1 = ld32h(sAlo, base + 8 * WK_STRIDE);
            uint32_t al2 = ld32h(sAlo, base + 8);
            uint32_t al3 = ld32h(sAlo, base + 8 * WK_STRIDE + 8);
            #pragma unroll
            for (int j = 0; j < 4; ++j)
                mma16(acc[m][j], ah0, ah1, ah2, ah3, bh[j][0], bh[j][1]);  // hi
            #pragma unroll
            for (int j = 0; j < 4; ++j)
                mma16(acc[m][j], al0, al1, al2, al3, bh[j][0], bh[j][1]);  // lo
        }
    }
}

// ---------------------------------------------------------------------------
// fused 2-layer MLP on mma.sync fp16 2-product split:
//   h = relu(agg @ W1 + b1);  y = h @ W2 + b2; (relu?) ; out = y + x
// Block: 256 threads, 64-row tile, 3 CTAs/SM (69.6KB smem).
// ---------------------------------------------------------------------------
__global__ void __launch_bounds__(256, 3)
k_mlp(const float* __restrict__ agg, const float* __restrict__ xin,
      const unsigned short* __restrict__ wbase, const float* __restrict__ b1,
      const float* __restrict__ b2, float* __restrict__ xout,
      int n, int relu_out) {
    extern __shared__ __align__(16) unsigned short smh[];
    unsigned short* sAhi = smh;                       // 64 x 136
    unsigned short* sAlo = smh + SA_HALFS;
    unsigned short* sWhi = smh + 2 * SA_HALFS;        // 128 x 136

    const int tid = threadIdx.x;
    const int lane = tid & 31;
    const int warp = tid >> 5;
    const int rowb = (warp >> 2) * 32;      // 0 or 32
    const int colb = (warp & 3) * 32;       // 0,32,64,96
    const int row0 = blockIdx.x * TILE_M;
    const int kq = lane & 3, nq = lane >> 2;

    // load + split A tile (agg already = scatter_sum + x; pad rows are zero)
    {
        const float4* aggv = reinterpret_cast<const float4*>(agg);
        for (int i = tid; i < 64 * 32; i += 256) {
            int r = i >> 5, kv = i & 31;
            float4 v = aggv[(size_t)(row0 + r) * H4 + kv];
            float h0, l0, h1, l1, h2, l2, h3, l3;
            split_fp16(v.x, h0, l0); split_fp16(v.y, h1, l1);
            split_fp16(v.z, h2, l2); split_fp16(v.w, h3, l3);
            int off = r * WK_STRIDE + kv * 4;
            *reinterpret_cast<uint2*>(sAhi + off) =
                make_uint2(pack_fp16(h0, h1), pack_fp16(h2, h3));
            *reinterpret_cast<uint2*>(sAlo + off) =
                make_uint2(pack_fp16(l0, l1), pack_fp16(l2, l3));
        }
    }
    // load W1 (identical layout -> linear vector copy)
    {
        const uint4* whi = reinterpret_cast<const uint4*>(wbase);
        for (int i = tid; i < W_HALFS / 8; i += 256)
            reinterpret_cast<uint4*>(sWhi)[i] = whi[i];
    }
    __syncthreads();

    float acc[2][4][4];
    #pragma unroll
    for (int m = 0; m < 2; ++m)
        #pragma unroll
        for (int j = 0; j < 4; ++j)
            #pragma unroll
            for (int c = 0; c < 4; ++c) acc[m][j][c] = 0.f;

    gemm_layer(sAhi, sAlo, sWhi, rowb, colb, nq, kq, acc);

    __syncthreads();   // everyone done reading A / W1 slots

    // epilogue 1: h = relu(D + b1) -> split back into sAhi/sAlo; load W2 tile
    #pragma unroll
    for (int j = 0; j < 4; ++j) {
        int n0 = colb + j * 8 + kq * 2;
        float2 bv = *reinterpret_cast<const float2*>(&b1[n0]);
        #pragma unroll
        for (int m = 0; m < 2; ++m) {
            int r = rowb + m * 16 + nq;
            float v0 = fmaxf(acc[m][j][0] + bv.x, 0.f);
            float v1 = fmaxf(acc[m][j][1] + bv.y, 0.f);
            float v2 = fmaxf(acc[m][j][2] + bv.x, 0.f);
            float v3 = fmaxf(acc[m][j][3] + bv.y, 0.f);
            float h0, l0, h1, l1, h2, l2, h3, l3;
            split_fp16(v0, h0, l0); split_fp16(v1, h1, l1);
            split_fp16(v2, h2, l2); split_fp16(v3, h3, l3);
            *reinterpret_cast<uint32_t*>(sAhi + r * WK_STRIDE + n0) = pack_fp16(h0, h1);
            *reinterpret_cast<uint32_t*>(sAlo + r * WK_STRIDE + n0) = pack_fp16(l0, l1);
            *reinterpret_cast<uint32_t*>(sAhi + (r + 8) * WK_STRIDE + n0) = pack_fp16(h2, h3);
            *reinterpret_cast<uint32_t*>(sAlo + (r + 8) * WK_STRIDE + n0) = pack_fp16(l2, l3);
        }
    }
    {
        const uint4* whi = reinterpret_cast<const uint4*>(wbase + W_HALFS);
        for (int i = tid; i < W_HALFS / 8; i += 256)
            reinterpret_cast<uint4*>(sWhi)[i] = whi[i];
    }
    __syncthreads();

    #pragma unroll
    for (int m = 0; m < 2; ++m)
        #pragma unroll
        for (int j = 0; j < 4; ++j)
            #pragma unroll
            for (int c = 0; c < 4; ++c) acc[m][j][c] = 0.f;

    gemm_layer(sAhi, sAlo, sWhi, rowb, colb, nq, kq, acc);

    // epilogue 2: y = D + b2 (+relu) + x ; store to gmem
    #pragma unroll
    for (int j = 0; j < 4; ++j) {
        int n0 = colb + j * 8 + kq * 2;
        float2 bv = *reinterpret_cast<const float2*>(&b2[n0]);
        #pragma unroll
        for (int m = 0; m < 2; ++m) {
            int r = rowb + m * 16 + nq;
            int gr0 = row0 + r;
            int gr1 = gr0 + 8;
            float y0 = acc[m][j][0] + bv.x, y1 = acc[m][j][1] + bv.y;
            float y2 = acc[m][j][2] + bv.x, y3 = acc[m][j][3] + bv.y;
            if (relu_out) {
                y0 = fmaxf(y0, 0.f); y1 = fmaxf(y1, 0.f);
                y2 = fmaxf(y2, 0.f); y3 = fmaxf(y3, 0.f);
            }
            if (gr0 < n) {
                float2 xv = *reinterpret_cast<const float2*>(&xin[(size_t)gr0 * H + n0]);
                *reinterpret_cast<float2*>(&xout[(size_t)gr0 * H + n0]) =
                    make_float2(y0 + xv.x, y1 + xv.y);
            }
            if (gr1 < n) {
                float2 xv = *reinterpret_cast<const float2*>(&xin[(size_t)gr1 * H + n0]);
                *reinterpret_cast<float2*>(&xout[(size_t)gr1 * H + n0]) =
                    make_float2(y2 + xv.x, y3 + xv.y);
            }
        }
    }
}

// ---------------------------------------------------------------------------
extern "C" void kernel_launch(void* const* d_in, const int* in_sizes, int n_in,
                              void* d_out, int out_size) {
    const int*   z   = (const int*)d_in[0];
    const int*   ei  = (const int*)d_in[1];
    const float* ea  = (const float*)d_in[2];
    const float* emb = (const float*)d_in[3];
    const float* W1  = (const float*)d_in[4];
    const float* b1  = (const float*)d_in[5];
    const float* W2  = (const float*)d_in[6];
    const float* b2  = (const float*)d_in[7];
    float* out = (float*)d_out;

    const int n = in_sizes[0];
    const int E = in_sizes[1] / 2;

    float *xbuf, *aggbuf;
    unsigned short* wsplit;
    int* degp;
    cudaGetSymbolAddress((void**)&xbuf, g_x);
    cudaGetSymbolAddress((void**)&aggbuf, g_agg);
    cudaGetSymbolAddress((void**)&wsplit, g_wsplit);
    cudaGetSymbolAddress((void**)&degp, g_deg);

    cudaFuncSetAttribute(k_mlp, cudaFuncAttributeMaxDynamicSharedMemorySize,
                         MLP_SMEM_BYTES);

    // ---- prologue: zero deg, then merged hist+embed+wsplit ----
    cudaMemsetAsync(degp, 0, (size_t)n * sizeof(int), 0);
    const int HB = (E + 255) / 256;
    const int EB = (n * 32 + 255) / 256;
    k_prep<<<HB + EB + 6, 256>>>(ei, E, z, emb, xbuf, n, W1, W2, HB, EB);

    // ---- CSR scan + fill (once; reused by all 3 convs) ----
    const int NB = (n + 1023) / 1024;
    k_scan1<<<NB, 1024>>>(n);
    k_scan3<<<NB, 1024>>>(n, E);
    k_fill<<<(E + 255) / 256, 256>>>(ei, E);

    const int gatherBlocks = (n * 32 + 255) / 256;   // 1 warp per node
    const int mlpBlocks = (n + TILE_M - 1) / TILE_M;

    for (int i = 0; i < 3; ++i) {
        k_gather<<<gatherBlocks, 256>>>(ea, xbuf, aggbuf, n);
        float* dst = (i == 2) ? out : xbuf;
        k_mlp<<<mlpBlocks, 256, MLP_SMEM_BYTES>>>(aggbuf, xbuf,
                                                  wsplit + (size_t)i * 2 * W_HALFS,
                                                  b1 + i * H, b2 + i * H,
                                                  dst, n, (i < 2) ? 1 : 0);
    }
}